// round 1
// baseline (speedup 1.0000x reference)
#include <cuda_runtime.h>
#include <cuda_bf16.h>

// CompositeValueNoise: out[i] = sum over levels L in {16,32,64,128} of
//   mult_L * trilinear(V_L, x[i]*L), mult_L = 16/L, fields = 4.
//
// One thread per point. 4 levels fully unrolled (res is compile-time after
// unroll). Each corner is a contiguous float4 (field dim innermost); the two
// corners along the innermost spatial dim are adjacent in memory, so the
// (k, k+1) pair shares L2 sectors.

#define N_FIELDS 4

__device__ __forceinline__ float4 ld4(const float* __restrict__ p) {
    return __ldg(reinterpret_cast<const float4*>(p));
}

__device__ __forceinline__ float4 lerp4(float4 a, float4 b, float w) {
    float4 r;
    r.x = fmaf(w, b.x - a.x, a.x);
    r.y = fmaf(w, b.y - a.y, a.y);
    r.z = fmaf(w, b.z - a.z, a.z);
    r.w = fmaf(w, b.w - a.w, a.w);
    return r;
}

__global__ void __launch_bounds__(256) composite_value_noise_kernel(
    const float* __restrict__ x,
    const float* __restrict__ V16,
    const float* __restrict__ V32,
    const float* __restrict__ V64,
    const float* __restrict__ V128,
    float* __restrict__ out,
    int n)
{
    int i = blockIdx.x * blockDim.x + threadIdx.x;
    if (i >= n) return;

    const float px = __ldg(x + 3 * i + 0);
    const float py = __ldg(x + 3 * i + 1);
    const float pz = __ldg(x + 3 * i + 2);

    const float* grids[4] = {V16, V32, V64, V128};
    const int    ress[4]  = {16, 32, 64, 128};

    float4 acc = make_float4(0.f, 0.f, 0.f, 0.f);

    #pragma unroll
    for (int L = 0; L < 4; ++L) {
        const float* __restrict__ V = grids[L];
        const int   res  = ress[L];
        const float resf = (float)res;
        const float mult = 16.0f / resf;

        // xs = fmod(x*res, res); x in [0,1) so this is effectively identity,
        // but keep fmod semantics for safety at the boundary.
        float xs = fmodf(px * resf, resf);
        float ys = fmodf(py * resf, resf);
        float zs = fmodf(pz * resf, resf);

        float fx = floorf(xs), fy = floorf(ys), fz = floorf(zs);
        float tx = xs - fx,    ty = ys - fy,    tz = zs - fz;

        int i0 = (int)fx, j0 = (int)fy, k0 = (int)fz;

        // smoothstep weights: w = (3 - 2t) * t * t
        float wx = (3.0f - 2.0f * tx) * tx * tx;
        float wy = (3.0f - 2.0f * ty) * ty * ty;
        float wz = (3.0f - 2.0f * tz) * tz * tz;

        const int r1 = res + 1;
        const int s1 = r1 * N_FIELDS;        // stride of dim 1 (floats)
        const int s0 = r1 * s1;              // stride of dim 0 (floats)

        const float* base = V + (size_t)i0 * s0 + (size_t)j0 * s1 + (size_t)k0 * N_FIELDS;

        // corners v[i][j][k], each a float4 of fields
        float4 v000 = ld4(base);
        float4 v001 = ld4(base + N_FIELDS);
        float4 v010 = ld4(base + s1);
        float4 v011 = ld4(base + s1 + N_FIELDS);
        float4 v100 = ld4(base + s0);
        float4 v101 = ld4(base + s0 + N_FIELDS);
        float4 v110 = ld4(base + s0 + s1);
        float4 v111 = ld4(base + s0 + s1 + N_FIELDS);

        // reduce dim0 with wx (matches reference order)
        float4 a00 = lerp4(v000, v100, wx);
        float4 a01 = lerp4(v001, v101, wx);
        float4 a10 = lerp4(v010, v110, wx);
        float4 a11 = lerp4(v011, v111, wx);
        // reduce dim1 with wy
        float4 b0 = lerp4(a00, a10, wy);
        float4 b1 = lerp4(a01, a11, wy);
        // reduce dim2 with wz
        float4 c = lerp4(b0, b1, wz);

        acc.x = fmaf(mult, c.x, acc.x);
        acc.y = fmaf(mult, c.y, acc.y);
        acc.z = fmaf(mult, c.z, acc.z);
        acc.w = fmaf(mult, c.w, acc.w);
    }

    reinterpret_cast<float4*>(out)[i] = acc;
}

extern "C" void kernel_launch(void* const* d_in, const int* in_sizes, int n_in,
                              void* d_out, int out_size) {
    const float* x    = (const float*)d_in[0];
    const float* V16  = (const float*)d_in[1];
    const float* V32  = (const float*)d_in[2];
    const float* V64  = (const float*)d_in[3];
    const float* V128 = (const float*)d_in[4];
    float* out = (float*)d_out;

    int n = in_sizes[0] / 3;  // N_POINTS
    int threads = 256;
    int blocks = (n + threads - 1) / threads;
    composite_value_noise_kernel<<<blocks, threads>>>(x, V16, V32, V64, V128, out, n);
}

// round 2
// speedup vs baseline: 1.6065x; 1.6065x over previous
#include <cuda_runtime.h>
#include <cuda_bf16.h>

// CompositeValueNoise, 2-threads-per-point version.
// Even lane of each pair owns corner k0, odd lane owns k0+1. The two 16B
// corner float4s are contiguous 32B, and living in the SAME LDG.128
// instruction across the lane pair lets L1 merge them into one wavefront,
// halving L1tex wavefront traffic (the R1 bottleneck: L1=87.7%).
// k-dim lerp is done with 4 shfl_xor(1) per level after the y-interp.

#define N_FIELDS 4

__device__ __forceinline__ float4 ld4(const float* __restrict__ p) {
    return __ldg(reinterpret_cast<const float4*>(p));
}

__device__ __forceinline__ float4 lerp4(float4 a, float4 b, float w) {
    float4 r;
    r.x = fmaf(w, b.x - a.x, a.x);
    r.y = fmaf(w, b.y - a.y, a.y);
    r.z = fmaf(w, b.z - a.z, a.z);
    r.w = fmaf(w, b.w - a.w, a.w);
    return r;
}

__global__ void __launch_bounds__(256) composite_value_noise_kernel(
    const float* __restrict__ x,
    const float* __restrict__ V16,
    const float* __restrict__ V32,
    const float* __restrict__ V64,
    const float* __restrict__ V128,
    float* __restrict__ out,
    int n)
{
    int gtid = blockIdx.x * blockDim.x + threadIdx.x;
    int p  = gtid >> 1;       // point index
    int kk = gtid & 1;        // which k corner this lane owns
    if (p >= n) return;

    // Both lanes of the pair read the same address -> broadcast in L1.
    const float px = __ldg(x + 3 * p + 0);
    const float py = __ldg(x + 3 * p + 1);
    const float pz = __ldg(x + 3 * p + 2);

    const float* grids[4] = {V16, V32, V64, V128};
    const int    ress[4]  = {16, 32, 64, 128};

    float4 acc = make_float4(0.f, 0.f, 0.f, 0.f);

    #pragma unroll
    for (int L = 0; L < 4; ++L) {
        const float* __restrict__ V = grids[L];
        const int   res  = ress[L];
        const float resf = (float)res;
        const float mult = 16.0f / resf;

        float xs = fmodf(px * resf, resf);
        float ys = fmodf(py * resf, resf);
        float zs = fmodf(pz * resf, resf);

        float fx = floorf(xs), fy = floorf(ys), fz = floorf(zs);
        float tx = xs - fx,    ty = ys - fy,    tz = zs - fz;

        int i0 = (int)fx, j0 = (int)fy, k0 = (int)fz;

        float wx = (3.0f - 2.0f * tx) * tx * tx;
        float wy = (3.0f - 2.0f * ty) * ty * ty;
        float wz = (3.0f - 2.0f * tz) * tz * tz;

        const int r1 = res + 1;
        const int s1 = r1 * N_FIELDS;   // dim-1 stride (floats)
        const int s0 = r1 * s1;         // dim-0 stride (floats)

        // This lane's k corner (k0 or k0+1); the pair's addresses are
        // contiguous 32B within each load instruction below.
        const float* base = V + (size_t)i0 * s0 + (size_t)j0 * s1
                              + (size_t)(k0 + kk) * N_FIELDS;

        float4 v00 = ld4(base);            // (i0, j0, k)
        float4 v01 = ld4(base + s1);       // (i0, j1, k)
        float4 v10 = ld4(base + s0);       // (i1, j0, k)
        float4 v11 = ld4(base + s0 + s1);  // (i1, j1, k)

        // reference order: dim0 (wx), dim1 (wy), then dim2 (wz) cross-lane
        float4 a0 = lerp4(v00, v10, wx);
        float4 a1 = lerp4(v01, v11, wx);
        float4 b  = lerp4(a0, a1, wy);     // value at this lane's k corner

        float4 o;
        o.x = __shfl_xor_sync(0xffffffffu, b.x, 1);
        o.y = __shfl_xor_sync(0xffffffffu, b.y, 1);
        o.z = __shfl_xor_sync(0xffffffffu, b.z, 1);
        o.w = __shfl_xor_sync(0xffffffffu, b.w, 1);

        // even lane: lo=b (k0), hi=o (k1); odd lane: lo=o, hi=b
        float4 lo = kk ? o : b;
        float4 hi = kk ? b : o;
        float4 c  = lerp4(lo, hi, wz);

        acc.x = fmaf(mult, c.x, acc.x);
        acc.y = fmaf(mult, c.y, acc.y);
        acc.z = fmaf(mult, c.z, acc.z);
        acc.w = fmaf(mult, c.w, acc.w);
    }

    // Both lanes hold the same acc. Split the 16B store across the pair so
    // the warp's stores are fully contiguous: even lane writes bytes [0,8),
    // odd lane writes bytes [8,16) of out[p].
    float2 half_val = kk ? make_float2(acc.z, acc.w) : make_float2(acc.x, acc.y);
    reinterpret_cast<float2*>(out)[2 * p + kk] = half_val;
}

extern "C" void kernel_launch(void* const* d_in, const int* in_sizes, int n_in,
                              void* d_out, int out_size) {
    const float* x    = (const float*)d_in[0];
    const float* V16  = (const float*)d_in[1];
    const float* V32  = (const float*)d_in[2];
    const float* V64  = (const float*)d_in[3];
    const float* V128 = (const float*)d_in[4];
    float* out = (float*)d_out;

    int n = in_sizes[0] / 3;          // N_POINTS
    long long total = 2LL * n;        // 2 threads per point
    int threads = 256;
    int blocks = (int)((total + threads - 1) / threads);
    composite_value_noise_kernel<<<blocks, threads>>>(x, V16, V32, V64, V128, out, n);
}